// round 1
// baseline (speedup 1.0000x reference)
#include <cuda_runtime.h>
#include <cstdint>

// Problem constants
#define MM      256
#define NN      128
#define TT      10
#define BATCH   65536
#define PDIM    512            // 2*M  (re||im output vector length)
#define TB      32             // batch rows per CTA
#define SSTR    520            // smem row stride (floats), 16B-aligned, depads conflicts
#define SMEM_BYTES (2 * TB * SSTR * 4)

// Real-expanded weight matrices, k-major: W[k][p]
__device__ float g_Wa[256 * PDIM];   // 512 KB
__device__ float g_Wb[PDIM * PDIM];  // 1 MB

// ---------------- f32x2 helpers (sm_103a packed fp32) ----------------
__device__ __forceinline__ unsigned long long pack2(float lo, float hi) {
    unsigned long long r;
    asm("mov.b64 %0, {%1, %2};" : "=l"(r) : "f"(lo), "f"(hi));
    return r;
}
__device__ __forceinline__ void fma2(unsigned long long& d,
                                     unsigned long long a,
                                     unsigned long long b) {
    asm("fma.rn.f32x2 %0, %1, %2, %0;" : "+l"(d) : "l"(a), "l"(b));
}
__device__ __forceinline__ float2 unpack2(unsigned long long v) {
    float2 f;
    asm("mov.b64 {%0, %1}, %2;" : "=f"(f.x), "=f"(f.y) : "l"(v));
    return f;
}

__device__ __forceinline__ float shrinkf(float v, float thr) {
    // eta*softshrink(v/eta, 1) == copysign(max(|v|-eta,0), v)   (thr = eta*LAMBD)
    float s = fmaxf(fabsf(v) - thr, 0.0f);
    return copysignf(s, v);
}

// ---------------- prep: expand complex A,B into real block matrices ----------------
// Wa[k][p], k in [0,256): k<128 -> y_re[q=k], else y_im[q=k-128]
//   p<256 (re out): [ Ar[p][q] | -Ai[p][q] ] ;  p>=256 (im out): [ Ai | Ar ]
// Wb[k][p], k in [0,512) analogous with B (256x256).
__global__ void prep_kernel(const float* __restrict__ A, const float* __restrict__ B) {
    int i = blockIdx.x * blockDim.x + threadIdx.x;
    // Wa: 256*512 = 131072 entries (grid covers exactly with 512x256)
    if (i < 256 * PDIM) {
        int k = i >> 9, p = i & 511;
        float v;
        if (k < 128) {
            if (p < 256) v =  A[p * NN + k];                       // Ar[p][k]
            else         v =  A[MM * NN + (p - 256) * NN + k];     // Ai[p-256][k]
        } else {
            int q = k - 128;
            if (p < 256) v = -A[MM * NN + p * NN + q];             // -Ai[p][q]
            else         v =  A[(p - 256) * NN + q];               // Ar[p-256][q]
        }
        g_Wa[i] = v;
    }
    // Wb: 512*512 entries, grid-stride
    int stride = gridDim.x * blockDim.x;
    for (int j = i; j < PDIM * PDIM; j += stride) {
        int k = j >> 9, p = j & 511;
        float v;
        if (k < 256) {
            if (p < 256) v =  B[p * MM + k];                        // Br[p][k]
            else         v =  B[MM * MM + (p - 256) * MM + k];      // Bi[p-256][k]
        } else {
            int q = k - 256;
            if (p < 256) v = -B[MM * MM + p * MM + q];              // -Bi[p][q]
            else         v =  B[(p - 256) * MM + q];                // Br[p-256][q]
        }
        g_Wb[j] = v;
    }
}

// ---------------- inner GEMM: acc[b-pair][out] += v[b][k] * W[k][p] ----------------
// vsm: smem [b][k] rows with stride SSTR, thread reads its 8 batch rows (broadcast
// within warp). W: global k-major, 8 consecutive outputs -> two float4 LDGs (L2-resident).
template <int K>
__device__ __forceinline__ void gemm_acc(unsigned long long acc[32],
                                         const float* __restrict__ vsm,
                                         const float* __restrict__ W,
                                         int to, int tb) {
#pragma unroll
    for (int r = 0; r < 32; ++r) acc[r] = 0ULL;

    const float* wcol = W + to;
#pragma unroll 2
    for (int k = 0; k < K; ++k) {
        float4 wa = *reinterpret_cast<const float4*>(wcol + (size_t)k * PDIM);
        float4 wb = *reinterpret_cast<const float4*>(wcol + (size_t)k * PDIM + 4);
        unsigned long long wd[8];
        wd[0] = pack2(wa.x, wa.x); wd[1] = pack2(wa.y, wa.y);
        wd[2] = pack2(wa.z, wa.z); wd[3] = pack2(wa.w, wa.w);
        wd[4] = pack2(wb.x, wb.x); wd[5] = pack2(wb.y, wb.y);
        wd[6] = pack2(wb.z, wb.z); wd[7] = pack2(wb.w, wb.w);

        unsigned long long vp[4];
#pragma unroll
        for (int i = 0; i < 4; ++i) {
            float vlo = vsm[(tb + 2 * i) * SSTR + k];
            float vhi = vsm[(tb + 2 * i + 1) * SSTR + k];
            vp[i] = pack2(vlo, vhi);
        }
#pragma unroll
        for (int i = 0; i < 4; ++i)
#pragma unroll
            for (int j = 0; j < 8; ++j)
                fma2(acc[i * 8 + j], vp[i], wd[j]);
    }
}

// ---------------- main fused kernel ----------------
// One CTA: 32 batch rows. smem: xs[32][520], ays[32][520]. 256 threads,
// thread tile = 8 batch x 8 outputs (batch packed pairwise into f32x2).
__global__ __launch_bounds__(256, 1)
void lista_main(const float* __restrict__ y,
                const float* __restrict__ etas,
                const float* __restrict__ gammas,
                float* __restrict__ out) {
    extern __shared__ float sm[];
    float* xs  = sm;                 // [TB][SSTR]
    float* ays = sm + TB * SSTR;     // [TB][SSTR]

    const int tid = threadIdx.x;
    const long b0 = (long)blockIdx.x * TB;
    const int to = (tid & 63) << 3;  // output start (0..504 step 8)
    const int tb = (tid >> 6) << 3;  // batch start within tile (0,8,16,24)

    // Stage y -> ays as ys[b][k'], k' = c*128+q  (coalesced global reads)
    for (int i = tid; i < TB * 256; i += 256) {
        int b = i >> 8, r = i & 255;
        int q = r >> 1, c = r & 1;
        ays[b * SSTR + c * 128 + q] = y[b0 * 256 + i];
    }
    __syncthreads();

    unsigned long long acc[32];

    // -------- Phase A: Ay = ys @ Wa, x0 = shrink(g0*Ay, e0) --------
    gemm_acc<256>(acc, ays, g_Wa, to, tb);
    {
        float g = gammas[0];
        float e = etas[0];
        __syncthreads();  // all gemm reads of ys done before overwriting ays
#pragma unroll
        for (int i = 0; i < 4; ++i) {
#pragma unroll
            for (int h = 0; h < 2; ++h) {
                int b = tb + 2 * i + h;
                float* arow = ays + b * SSTR + to;
                float* xrow = xs  + b * SSTR + to;
#pragma unroll
                for (int jj = 0; jj < 8; jj += 4) {
                    float4 av, xv;
                    float2 p0 = unpack2(acc[i * 8 + jj + 0]);
                    float2 p1 = unpack2(acc[i * 8 + jj + 1]);
                    float2 p2 = unpack2(acc[i * 8 + jj + 2]);
                    float2 p3 = unpack2(acc[i * 8 + jj + 3]);
                    av.x = h ? p0.y : p0.x;
                    av.y = h ? p1.y : p1.x;
                    av.z = h ? p2.y : p2.x;
                    av.w = h ? p3.y : p3.x;
                    xv.x = shrinkf(g * av.x, e);
                    xv.y = shrinkf(g * av.y, e);
                    xv.z = shrinkf(g * av.z, e);
                    xv.w = shrinkf(g * av.w, e);
                    *reinterpret_cast<float4*>(arow + jj) = av;
                    *reinterpret_cast<float4*>(xrow + jj) = xv;
                }
            }
        }
    }
    __syncthreads();

    // -------- 10 iterations: x = shrink(x + g*(Ay - Bx), e) --------
    for (int t = 1; t <= TT; ++t) {
        gemm_acc<PDIM>(acc, xs, g_Wb, to, tb);
        float g = gammas[t];
        float e = etas[t];
        __syncthreads();  // all gemm reads of xs complete before in-place update
#pragma unroll
        for (int i = 0; i < 4; ++i) {
#pragma unroll
            for (int h = 0; h < 2; ++h) {
                int b = tb + 2 * i + h;
                float* xrow = xs  + b * SSTR + to;
                const float* arow = ays + b * SSTR + to;
#pragma unroll
                for (int jj = 0; jj < 8; jj += 4) {
                    float4 xo = *reinterpret_cast<const float4*>(xrow + jj);
                    float4 av = *reinterpret_cast<const float4*>(arow + jj);
                    float2 p0 = unpack2(acc[i * 8 + jj + 0]);
                    float2 p1 = unpack2(acc[i * 8 + jj + 1]);
                    float2 p2 = unpack2(acc[i * 8 + jj + 2]);
                    float2 p3 = unpack2(acc[i * 8 + jj + 3]);
                    float bx0 = h ? p0.y : p0.x;
                    float bx1 = h ? p1.y : p1.x;
                    float bx2 = h ? p2.y : p2.x;
                    float bx3 = h ? p3.y : p3.x;
                    float4 nv;
                    nv.x = shrinkf(fmaf(g, av.x - bx0, xo.x), e);
                    nv.y = shrinkf(fmaf(g, av.y - bx1, xo.y), e);
                    nv.z = shrinkf(fmaf(g, av.z - bx2, xo.z), e);
                    nv.w = shrinkf(fmaf(g, av.w - bx3, xo.w), e);
                    *reinterpret_cast<float4*>(xrow + jj) = nv;
                }
            }
        }
        __syncthreads();
    }

    // -------- output: out[b][p][c] = x[c*256+p]  (coalesced global writes) --------
    for (int i = tid; i < TB * PDIM; i += 256) {
        int b = i >> 9, r = i & 511;
        int p = r >> 1, c = r & 1;
        out[b0 * PDIM + i] = xs[b * SSTR + c * 256 + p];
    }
}

extern "C" void kernel_launch(void* const* d_in, const int* in_sizes, int n_in,
                              void* d_out, int out_size) {
    const float* y      = (const float*)d_in[0];
    const float* A      = (const float*)d_in[1];
    const float* B      = (const float*)d_in[2];
    const float* etas   = (const float*)d_in[3];
    const float* gammas = (const float*)d_in[4];
    float* out = (float*)d_out;

    // Expand complex weights into real block matrices (k-major)
    prep_kernel<<<512, 256>>>(A, B);

    cudaFuncSetAttribute(lista_main, cudaFuncAttributeMaxDynamicSharedMemorySize,
                         SMEM_BYTES);
    lista_main<<<BATCH / TB, 256, SMEM_BYTES>>>(y, etas, gammas, out);
}

// round 3
// speedup vs baseline: 4.2568x; 4.2568x over previous
#include <cuda_runtime.h>
#include <cuda_fp16.h>
#include <cstdint>

#define TT        10
#define NB        32                 // batch rows per CTA
#define THREADS   512
#define NCTA      (65536 / NB)       // 2048

// smem layout (bytes)
#define XH_OFF    0                  // x hi: 512 k-rows x 32 n x 2B = 32KB
#define XL_OFF    32768
#define W_OFF     65536              // 2 bufs x (Wh 32KB + Wl 32KB)
#define SMEM_TOTAL (65536 + 2 * 65536)   // 192KB

// W chunk arrays, pre-swizzled: chunk = K-slab of 32, layout [p=512][kk=32] halves
__device__ __half g_WbH[16 * 16384];   // 512KB
__device__ __half g_WbL[16 * 16384];
__device__ __half g_WaH[8 * 16384];    // 256KB
__device__ __half g_WaL[8 * 16384];

// ---------------- PTX helpers ----------------
static __device__ __forceinline__ uint32_t smem_u32(const void* p) {
    uint32_t a;
    asm("{ .reg .u64 t; cvta.to.shared.u64 t, %1; cvt.u32.u64 %0, t; }" : "=r"(a) : "l"(p));
    return a;
}
static __device__ __forceinline__ void cp16(uint32_t s, const void* g) {
    asm volatile("cp.async.cg.shared.global [%0], [%1], 16;" :: "r"(s), "l"(g));
}
static __device__ __forceinline__ void ldmA(uint32_t* r, uint32_t addr) {
    asm volatile("ldmatrix.sync.aligned.m8n8.x4.shared.b16 {%0,%1,%2,%3}, [%4];"
                 : "=r"(r[0]), "=r"(r[1]), "=r"(r[2]), "=r"(r[3]) : "r"(addr));
}
static __device__ __forceinline__ void ldmB(uint32_t* r, uint32_t addr) {
    asm volatile("ldmatrix.sync.aligned.m8n8.x2.trans.shared.b16 {%0,%1}, [%2];"
                 : "=r"(r[0]), "=r"(r[1]) : "r"(addr));
}
static __device__ __forceinline__ void mma16816(float* d, const uint32_t* a, const uint32_t* b) {
    asm volatile("mma.sync.aligned.m16n8k16.row.col.f32.f16.f16.f32 "
                 "{%0,%1,%2,%3}, {%4,%5,%6,%7}, {%8,%9}, {%0,%1,%2,%3};"
                 : "+f"(d[0]), "+f"(d[1]), "+f"(d[2]), "+f"(d[3])
                 : "r"(a[0]), "r"(a[1]), "r"(a[2]), "r"(a[3]), "r"(b[0]), "r"(b[1]));
}

// Swizzle for 64B rows: XOR 16B-slot bits [5:4] with row bits [2:1].
// x plane: row = k (32 n * 2B); W chunk: row = p (32 kk * 2B).
static __device__ __host__ __forceinline__ uint32_t swz64(int row, int colbyte) {
    return (uint32_t)(row * 64 + (colbyte ^ ((row & 6) << 3)));
}

// ---------------- prep: expand complex A,B -> fp16 hi/lo swizzled chunks ----------------
__global__ void prep_kernel(const float* __restrict__ A, const float* __restrict__ B) {
    for (int i = blockIdx.x * blockDim.x + threadIdx.x; i < 393216;
         i += gridDim.x * blockDim.x) {
        float v;
        int dest;
        __half *dH, *dL;
        if (i < 262144) {                        // B matrix: 16 chunks
            int chunk = i >> 14, inner = i & 16383, p = inner >> 5, kk = inner & 31;
            int k = chunk * 32 + kk;
            if (k < 256) v = (p < 256) ? B[p * 256 + k] : B[65536 + (p - 256) * 256 + k];
            else { int q = k - 256; v = (p < 256) ? -B[65536 + p * 256 + q] : B[(p - 256) * 256 + q]; }
            dest = chunk * 16384 + (int)(swz64(p, kk * 2) >> 1);
            dH = g_WbH; dL = g_WbL;
        } else {                                  // A matrix: 8 chunks
            int j = i - 262144;
            int chunk = j >> 14, inner = j & 16383, p = inner >> 5, kk = inner & 31;
            int k = chunk * 32 + kk;
            if (k < 128) v = (p < 256) ? A[p * 128 + k] : A[32768 + (p - 256) * 128 + k];
            else { int q = k - 128; v = (p < 256) ? -A[32768 + p * 128 + q] : A[(p - 256) * 128 + q]; }
            dest = chunk * 16384 + (int)(swz64(p, kk * 2) >> 1);
            dH = g_WaH; dL = g_WaL;
        }
        __half hi = __float2half_rn(v);
        dH[dest] = hi;
        dL[dest] = __float2half_rn(v - __half2float(hi));
    }
}

// ---------------- chunk loader: 64KB (Wh + Wl) via cp.async ----------------
static __device__ __forceinline__ void issue_chunk(uint32_t sbuf, const __half* gH,
                                                   const __half* gL, int c, int tid) {
    const char* srcH = (const char*)gH + (size_t)c * 32768;
    const char* srcL = (const char*)gL + (size_t)c * 32768;
#pragma unroll
    for (int u = 0; u < 4; ++u) {
        uint32_t o = (uint32_t)tid * 16 + (uint32_t)u * 8192;
        cp16(sbuf + o, srcH + o);
        cp16(sbuf + 32768 + o, srcL + o);
    }
}

// ---------------- GEMM pass: acc[p-tile][n-tile] += 3-term split W*x ----------------
static __device__ __forceinline__ void gemm_pass(
    uint32_t smb, const __half* gH, const __half* gL, int NC,
    float (*acc)[4], int mbase, int nbase, int tid, int lane)
{
    issue_chunk(smb + W_OFF, gH, gL, 0, tid);
    asm volatile("cp.async.commit_group;" ::: "memory");
    issue_chunk(smb + W_OFF + 65536, gH, gL, 1, tid);
    asm volatile("cp.async.commit_group;" ::: "memory");

    const int l15 = lane & 15;
    const uint32_t axor = (uint32_t)((l15 & 6) << 3);

    // A ldmatrix offsets within a W chunk buffer: 4 mtiles x 2 ksteps
    uint32_t aoff[4][2];
#pragma unroll
    for (int mt = 0; mt < 4; ++mt)
#pragma unroll
        for (int s = 0; s < 2; ++s)
            aoff[mt][s] = (uint32_t)(mbase + mt * 16 + l15) * 64
                        + (((uint32_t)(s * 32 + ((lane >> 4) * 16))) ^ axor);

    // B column-byte (XORed) per ntile
    uint32_t bcol[2];
#pragma unroll
    for (int nt = 0; nt < 2; ++nt)
        bcol[nt] = ((uint32_t)((nbase + nt * 8) * 2)) ^ axor;

#pragma unroll 1
    for (int c = 0; c < NC; ++c) {
        asm volatile("cp.async.wait_group 1;" ::: "memory");
        __syncthreads();
        const uint32_t wb = smb + W_OFF + (uint32_t)(c & 1) * 65536;
#pragma unroll
        for (int s = 0; s < 2; ++s) {
            const uint32_t krow = (uint32_t)(c * 32 + s * 16 + l15) * 64;
            uint32_t bh[2][2], bl[2][2];
#pragma unroll
            for (int nt = 0; nt < 2; ++nt) {
                ldmB(bh[nt], smb + XH_OFF + krow + bcol[nt]);
                ldmB(bl[nt], smb + XL_OFF + krow + bcol[nt]);
            }
#pragma unroll
            for (int mt = 0; mt < 4; ++mt) {
                uint32_t ah[4], al[4];
                ldmA(ah, wb + aoff[mt][s]);
                ldmA(al, wb + 32768 + aoff[mt][s]);
#pragma unroll
                for (int nt = 0; nt < 2; ++nt) {
                    mma16816(acc[mt * 2 + nt], ah, bh[nt]);   // Wh * xh
                    mma16816(acc[mt * 2 + nt], ah, bl[nt]);   // Wh * xl
                    mma16816(acc[mt * 2 + nt], al, bh[nt]);   // Wl * xh
                }
            }
        }
        __syncthreads();
        if (c + 2 < NC) issue_chunk(wb, gH, gL, c + 2, tid);
        asm volatile("cp.async.commit_group;" ::: "memory");
    }
}

// ---------------- main fused kernel ----------------
__global__ __launch_bounds__(THREADS, 1)
void lista_main(const float* __restrict__ y,
                const float* __restrict__ etas,
                const float* __restrict__ gammas,
                float* __restrict__ out) {
    extern __shared__ char smc[];
    const uint32_t smb = smem_u32(smc);
    const int tid = threadIdx.x, lane = tid & 31, wid = tid >> 5;
    const int mbase = (wid >> 1) * 64;        // 8 M-warps x 64 rows
    const int nbase = (wid & 1) * 16;         // 2 N-warps x 16 cols
    const long b0 = (long)blockIdx.x * NB;

    // stage y into x planes (rows 0..255): k = c*128 + q
    for (int idx = tid; idx < NB * 256; idx += THREADS) {
        int n = idx >> 8, j = idx & 255, q = j >> 1, cc = j & 1, k = cc * 128 + q;
        float v = y[(b0 + n) * 256 + j];
        __half hi = __float2half_rn(v);
        __half lo = __float2half_rn(v - __half2float(hi));
        uint32_t off = swz64(k, n * 2);
        *(__half*)(smc + XH_OFF + off) = hi;
        *(__half*)(smc + XL_OFF + off) = lo;
    }
    __syncthreads();

    float ay[8][4], d[8][4];
#pragma unroll
    for (int i = 0; i < 8; ++i)
#pragma unroll
        for (int j = 0; j < 4; ++j) ay[i][j] = 0.0f;

    // epilogue lane geometry
    const int eg = lane >> 2, ec = lane & 3;
    const uint32_t exor = (uint32_t)((eg & 6) << 3);

    // -------- Phase A: Ay = Wa * y (resident in regs) --------
    gemm_pass(smb, g_WaH, g_WaL, 8, ay, mbase, nbase, tid, lane);
    {
        const float g = gammas[0], e = etas[0];
#pragma unroll
        for (int mt = 0; mt < 4; ++mt)
#pragma unroll
            for (int nt = 0; nt < 2; ++nt)
#pragma unroll
                for (int rg = 0; rg < 2; ++rg) {
                    const int p = mbase + mt * 16 + eg + rg * 8;
                    const uint32_t ncb = (uint32_t)((nbase + nt * 8) * 2 + ec * 4);
                    const uint32_t off = (uint32_t)p * 64 + (ncb ^ exor);
                    const int ai = mt * 2 + nt;
                    float v0 = g * ay[ai][rg * 2 + 0];
                    float v1 = g * ay[ai][rg * 2 + 1];
                    float x0 = copysignf(fmaxf(fabsf(v0) - e, 0.0f), v0);
                    float x1 = copysignf(fmaxf(fabsf(v1) - e, 0.0f), v1);
                    __half h0 = __float2half_rn(x0), h1 = __float2half_rn(x1);
                    __half l0 = __float2half_rn(x0 - __half2float(h0));
                    __half l1 = __float2half_rn(x1 - __half2float(h1));
                    *(__half2*)(smc + XH_OFF + off) = __halves2half2(h0, h1);
                    *(__half2*)(smc + XL_OFF + off) = __halves2half2(l0, l1);
                }
    }
    // next gemm's first barrier orders these writes vs ldmatrix reads

    // -------- 10 iterations: x = shrink(x + g*(Ay - Bx), e) --------
#pragma unroll 1
    for (int t = 1; t <= TT; ++t) {
#pragma unroll
        for (int i = 0; i < 8; ++i)
#pragma unroll
            for (int j = 0; j < 4; ++j) d[i][j] = 0.0f;

        gemm_pass(smb, g_WbH, g_WbL, 16, d, mbase, nbase, tid, lane);

        const float g = gammas[t], e = etas[t];
#pragma unroll
        for (int mt = 0; mt < 4; ++mt)
#pragma unroll
            for (int nt = 0; nt < 2; ++nt)
#pragma unroll
                for (int rg = 0; rg < 2; ++rg) {
                    const int p = mbase + mt * 16 + eg + rg * 8;
                    const uint32_t ncb = (uint32_t)((nbase + nt * 8) * 2 + ec * 4);
                    const uint32_t off = (uint32_t)p * 64 + (ncb ^ exor);
                    const int ai = mt * 2 + nt;
                    __half2 hh = *(const __half2*)(smc + XH_OFF + off);
                    __half2 ll = *(const __half2*)(smc + XL_OFF + off);
                    float xo0 = __half2float(__low2half(hh)) + __half2float(__low2half(ll));
                    float xo1 = __half2float(__high2half(hh)) + __half2float(__high2half(ll));
                    float v0 = fmaf(g, ay[ai][rg * 2 + 0] - d[ai][rg * 2 + 0], xo0);
                    float v1 = fmaf(g, ay[ai][rg * 2 + 1] - d[ai][rg * 2 + 1], xo1);
                    float x0 = copysignf(fmaxf(fabsf(v0) - e, 0.0f), v0);
                    float x1 = copysignf(fmaxf(fabsf(v1) - e, 0.0f), v1);
                    __half h0 = __float2half_rn(x0), h1 = __float2half_rn(x1);
                    __half l0 = __float2half_rn(x0 - __half2float(h0));
                    __half l1 = __float2half_rn(x1 - __half2float(h1));
                    *(__half2*)(smc + XH_OFF + off) = __halves2half2(h0, h1);
                    *(__half2*)(smc + XL_OFF + off) = __halves2half2(l0, l1);
                }
    }

    __syncthreads();
    // output: out[b][m][c] = x[p = c*256 + m], coalesced fp32 writes
    for (int idx = tid; idx < NB * 512; idx += THREADS) {
        const int n = idx >> 9, i = idx & 511, m = i >> 1, cc = i & 1;
        const int p = cc * 256 + m;
        const uint32_t off = swz64(p, n * 2);
        const float v = __half2float(*(const __half*)(smc + XH_OFF + off))
                      + __half2float(*(const __half*)(smc + XL_OFF + off));
        out[(b0 + n) * 512 + i] = v;
    }
}

extern "C" void kernel_launch(void* const* d_in, const int* in_sizes, int n_in,
                              void* d_out, int out_size) {
    const float* y      = (const float*)d_in[0];
    const float* A      = (const float*)d_in[1];
    const float* B      = (const float*)d_in[2];
    const float* etas   = (const float*)d_in[3];
    const float* gammas = (const float*)d_in[4];
    float* out = (float*)d_out;

    prep_kernel<<<512, 256>>>(A, B);

    cudaFuncSetAttribute(lista_main, cudaFuncAttributeMaxDynamicSharedMemorySize, SMEM_TOTAL);
    lista_main<<<NCTA, THREADS, SMEM_TOTAL>>>(y, etas, gammas, out);
}